// round 1
// baseline (speedup 1.0000x reference)
#include <cuda_runtime.h>

// Problem constants (fixed by the dataset)
#define NB       2        // batch
#define SDIM     256      // S
#define FDIM     512      // F1 = F2
#define NNODES   20000    // N
#define NE_      320000   // E
#define NLAYERS  3
#define BSJ      512      // NB * SDIM

// ---------------- scratch (device globals; no runtime allocation) ----------
__device__ float g_nsum[(size_t)NNODES * FDIM];        // 41 MB
__device__ float g_CT  [(size_t)BSJ * FDIM];           // 1 MB  CT[j][f2]
__device__ float g_dvec[BSJ];
__device__ float g_hA  [(size_t)NB * NNODES * SDIM];   // 41 MB (h)
__device__ float g_hB  [(size_t)NB * NNODES * SDIM];   // 41 MB (hw)
__device__ int   g_deg [NNODES];
__device__ int   g_off [NNODES + 1];
__device__ int   g_cur [NNODES];
__device__ int   g_srcs[NE_];
__device__ float g_dinv[NNODES];

// ---------------- CSR build ------------------------------------------------
__global__ void k_init_deg() {
    int i = blockIdx.x * blockDim.x + threadIdx.x;
    if (i < NNODES) g_deg[i] = 1;   // self loop
}

__global__ void k_hist(const int* __restrict__ ei) {
    int e = blockIdx.x * blockDim.x + threadIdx.x;
    if (e < NE_) atomicAdd(&g_deg[ei[NE_ + e]], 1);
}

// single-block scan: offsets (exclusive scan of deg-1), cursors, dinv
__global__ void k_scan() {
    __shared__ int ssum[512];
    int tid = threadIdx.x;
    const int CH = (NNODES + 511) / 512;   // 40
    int base = tid * CH;
    int s = 0;
    for (int i = 0; i < CH; ++i) {
        int idx = base + i;
        if (idx < NNODES) s += g_deg[idx] - 1;
    }
    ssum[tid] = s;
    __syncthreads();
    for (int off = 1; off < 512; off <<= 1) {
        int v = ssum[tid];
        int u = (tid >= off) ? ssum[tid - off] : 0;
        __syncthreads();
        ssum[tid] = v + u;
        __syncthreads();
    }
    int run = (tid == 0) ? 0 : ssum[tid - 1];
    for (int i = 0; i < CH; ++i) {
        int idx = base + i;
        if (idx < NNODES) {
            g_off[idx] = run;
            g_cur[idx] = run;
            g_dinv[idx] = rsqrtf((float)g_deg[idx]);
            run += g_deg[idx] - 1;
        }
    }
    if (tid == 511) g_off[NNODES] = run;   // == NE_
}

__global__ void k_scatter(const int* __restrict__ ei) {
    int e = blockIdx.x * blockDim.x + threadIdx.x;
    if (e < NE_) {
        int d = ei[NE_ + e];
        int p = atomicAdd(&g_cur[d], 1);
        g_srcs[p] = ei[e];
    }
}

// ---------------- nsum[n,f] = nodes[n,0,f] + nodes[n,1,f] ------------------
__global__ void k_nsum(const float* __restrict__ nodes) {
    long i = (long)blockIdx.x * blockDim.x + threadIdx.x;
    const long total = (long)NNODES * FDIM / 4;
    if (i >= total) return;
    const float4* nd = (const float4*)nodes;
    float4* ns = (float4*)g_nsum;
    long n = i / (FDIM / 4);
    long f = i % (FDIM / 4);
    float4 a = nd[n * (2 * FDIM / 4) + f];
    float4 b = nd[n * (2 * FDIM / 4) + FDIM / 4 + f];
    ns[i] = make_float4(a.x + b.x, a.y + b.y, a.z + b.z, a.w + b.w);
}

// ---------------- dvec[j] = 2 * sum_k bp[k]*x[j,k] -------------------------
__global__ void k_dvec(const float* __restrict__ x, const float* __restrict__ bp) {
    __shared__ float sh[256];
    int j = blockIdx.x;
    float s = 0.f;
    for (int k = threadIdx.x; k < FDIM; k += 256)
        s += bp[k] * x[(long)j * FDIM + k];
    sh[threadIdx.x] = s;
    __syncthreads();
    for (int o = 128; o > 0; o >>= 1) {
        if (threadIdx.x < o) sh[threadIdx.x] += sh[threadIdx.x + o];
        __syncthreads();
    }
    if (threadIdx.x == 0) g_dvec[j] = 2.f * sh[0];
}

// ---------------- generic NN SGEMM: C[M,N] = A[M,K] * B[K,N] ---------------
// 128x128x8 tile, 256 threads, 8x8 per thread. N % 128 == 0, K % 8 == 0.
// blockIdx.z batches A and C via strides; B shared (strideB usually 0).
__global__ __launch_bounds__(256) void sgemm_nn(
    const float* __restrict__ A, const float* __restrict__ B, float* __restrict__ C,
    int M, int N, int K, long sA, long sB, long sC)
{
    A += (long)blockIdx.z * sA;
    B += (long)blockIdx.z * sB;
    C += (long)blockIdx.z * sC;
    __shared__ float As[8][128];
    __shared__ float Bs[8][128];
    int tid = threadIdx.x;
    int brow = blockIdx.x * 128;
    int bcol = blockIdx.y * 128;
    int tr = (tid / 16) * 8;
    int tc = (tid % 16) * 8;
    float acc[8][8] = {};
    int arow = tid / 2, acol = (tid % 2) * 4;
    int brl = tid / 32, bcl = (tid % 32) * 4;

    for (int k0 = 0; k0 < K; k0 += 8) {
        int gr = brow + arow;
        float4 av = (gr < M) ? *(const float4*)(A + (long)gr * K + k0 + acol)
                             : make_float4(0, 0, 0, 0);
        As[acol + 0][arow] = av.x; As[acol + 1][arow] = av.y;
        As[acol + 2][arow] = av.z; As[acol + 3][arow] = av.w;
        float4 bv = *(const float4*)(B + (long)(k0 + brl) * N + bcol + bcl);
        *(float4*)&Bs[brl][bcl] = bv;
        __syncthreads();
#pragma unroll
        for (int k = 0; k < 8; ++k) {
            float ar[8], br[8];
#pragma unroll
            for (int i = 0; i < 8; ++i) ar[i] = As[k][tr + i];
#pragma unroll
            for (int i = 0; i < 8; ++i) br[i] = Bs[k][tc + i];
#pragma unroll
            for (int i = 0; i < 8; ++i)
#pragma unroll
                for (int j = 0; j < 8; ++j)
                    acc[i][j] = fmaf(ar[i], br[j], acc[i][j]);
        }
        __syncthreads();
    }
#pragma unroll
    for (int i = 0; i < 8; ++i) {
        int gr = brow + tr + i;
        if (gr < M) {
#pragma unroll
            for (int j = 0; j < 8; j += 4) {
                *(float4*)(C + (long)gr * N + bcol + tc + j) =
                    make_float4(acc[i][j], acc[i][j + 1], acc[i][j + 2], acc[i][j + 3]);
            }
        }
    }
}

// ---------------- H0 GEMM (NT) with fused epilogue -------------------------
// h[b][n][s] = sum_f2 nsum[n,f2] * CT[b*256+s, f2] + dvec[b*256+s]
__global__ __launch_bounds__(256) void sgemm_nt_h0() {
    const int M = NNODES, K = FDIM;
    __shared__ float As[8][128];
    __shared__ float Bs[8][128];
    int tid = threadIdx.x;
    int brow = blockIdx.x * 128;
    int bcol = blockIdx.y * 128;        // j base (multiple of 128 -> single batch per tile)
    int tr = (tid / 16) * 8;
    int tc = (tid % 16) * 8;
    float acc[8][8] = {};
    int arow = tid / 2, acol = (tid % 2) * 4;
    int bnl = tid / 2, bkl = (tid % 2) * 4;

    for (int k0 = 0; k0 < K; k0 += 8) {
        int gr = brow + arow;
        float4 av = (gr < M) ? *(const float4*)(g_nsum + (long)gr * K + k0 + acol)
                             : make_float4(0, 0, 0, 0);
        As[acol + 0][arow] = av.x; As[acol + 1][arow] = av.y;
        As[acol + 2][arow] = av.z; As[acol + 3][arow] = av.w;
        float4 bv = *(const float4*)(g_CT + (long)(bcol + bnl) * K + k0 + bkl);
        Bs[bkl + 0][bnl] = bv.x; Bs[bkl + 1][bnl] = bv.y;
        Bs[bkl + 2][bnl] = bv.z; Bs[bkl + 3][bnl] = bv.w;
        __syncthreads();
#pragma unroll
        for (int k = 0; k < 8; ++k) {
            float ar[8], br[8];
#pragma unroll
            for (int i = 0; i < 8; ++i) ar[i] = As[k][tr + i];
#pragma unroll
            for (int i = 0; i < 8; ++i) br[i] = Bs[k][tc + i];
#pragma unroll
            for (int i = 0; i < 8; ++i)
#pragma unroll
                for (int j = 0; j < 8; ++j)
                    acc[i][j] = fmaf(ar[i], br[j], acc[i][j]);
        }
        __syncthreads();
    }
    int b = bcol >> 8;                  // batch
    int j0 = bcol + tc;
    int s0 = j0 & 255;
#pragma unroll
    for (int i = 0; i < 8; ++i) {
        int gr = brow + tr + i;
        if (gr < M) {
            float* dst = g_hA + ((long)b * NNODES + gr) * SDIM + s0;
#pragma unroll
            for (int j = 0; j < 8; j += 4) {
                *(float4*)(dst + j) = make_float4(
                    acc[i][j + 0] + g_dvec[j0 + j + 0],
                    acc[i][j + 1] + g_dvec[j0 + j + 1],
                    acc[i][j + 2] + g_dvec[j0 + j + 2],
                    acc[i][j + 3] + g_dvec[j0 + j + 3]);
            }
        }
    }
}

// ---------------- CSR aggregation + bias + leaky relu ----------------------
// reads hw = g_hB, writes h = g_hA
__global__ void k_agg(const float* __restrict__ bias) {
    int t = blockIdx.x;
    int b = blockIdx.y;
    int s = threadIdx.x;
    float dt = g_dinv[t];
    long base = (long)b * NNODES * SDIM;
    float acc = g_hB[base + (long)t * SDIM + s] * dt * dt;   // self loop
    int e0 = g_off[t], e1 = g_off[t + 1];
    for (int e = e0; e < e1; ++e) {
        int src = g_srcs[e];
        float w = g_dinv[src] * dt;
        acc = fmaf(g_hB[base + (long)src * SDIM + s], w, acc);
    }
    acc += bias[s];
    g_hA[base + (long)t * SDIM + s] = acc > 0.f ? acc : 0.01f * acc;
}

// ---------------- output: out[b,n] = sum_s h[b,n,s]*wbp[s] + bbp -----------
__global__ void k_out(const float* __restrict__ wbp, const float* __restrict__ bbp,
                      float* __restrict__ out) {
    int gw = (blockIdx.x * blockDim.x + threadIdx.x) >> 5;
    int lane = threadIdx.x & 31;
    if (gw >= NB * NNODES) return;
    int b = gw / NNODES, n = gw % NNODES;
    const float* hr = g_hA + ((long)b * NNODES + n) * SDIM;
    float s = 0.f;
#pragma unroll
    for (int k = lane; k < SDIM; k += 32) s = fmaf(hr[k], wbp[k], s);
#pragma unroll
    for (int o = 16; o; o >>= 1) s += __shfl_xor_sync(0xffffffffu, s, o);
    if (lane == 0) out[(long)b * NNODES + n] = s + bbp[0];
}

// ---------------- launcher -------------------------------------------------
extern "C" void kernel_launch(void* const* d_in, const int* in_sizes, int n_in,
                              void* d_out, int out_size) {
    const float* x     = (const float*)d_in[0];   // [B,S,F]   = [2,256,512]
    const float* nodes = (const float*)d_in[1];   // [N,2,F]
    const int*   ei    = (const int*)  d_in[2];   // [2,E]
    const float* Wp    = (const float*)d_in[3];   // [F,F]
    const float* bp    = (const float*)d_in[4];   // [F]
    const float* gW    = (const float*)d_in[5];   // [L,S,S]
    const float* gb    = (const float*)d_in[6];   // [L,S]
    const float* wbp   = (const float*)d_in[7];   // [S]
    const float* bbp   = (const float*)d_in[8];   // [1]
    float* out = (float*)d_out;

    void *pCT, *pHA, *pHB;
    cudaGetSymbolAddress(&pCT, g_CT);
    cudaGetSymbolAddress(&pHA, g_hA);
    cudaGetSymbolAddress(&pHB, g_hB);
    float* CTp = (float*)pCT;
    float* hAp = (float*)pHA;
    float* hBp = (float*)pHB;

    // CSR build (re-done deterministically-enough each replay)
    k_init_deg<<<(NNODES + 255) / 256, 256>>>();
    k_hist<<<(NE_ + 255) / 256, 256>>>(ei);
    k_scan<<<1, 512>>>();
    k_scatter<<<(NE_ + 255) / 256, 256>>>(ei);

    // front-end
    k_nsum<<<(int)(((long)NNODES * FDIM / 4 + 255) / 256), 256>>>(nodes);
    // CT[j,f2] = sum_k x[j,k] * Wp[k,f2] : M=512,N=512,K=512
    sgemm_nn<<<dim3(4, 4, 1), 256>>>(x, Wp, CTp, BSJ, FDIM, FDIM, 0, 0, 0);
    k_dvec<<<BSJ, 256>>>(x, bp);
    // H0 into g_hA
    sgemm_nt_h0<<<dim3((NNODES + 127) / 128, BSJ / 128, 1), 256>>>();

    // GCN layers
    const long slab = (long)NNODES * SDIM;
    for (int l = 0; l < NLAYERS; ++l) {
        sgemm_nn<<<dim3((NNODES + 127) / 128, SDIM / 128, NB), 256>>>(
            hAp, gW + (long)l * SDIM * SDIM, hBp,
            NNODES, SDIM, SDIM, slab, 0, slab);
        k_agg<<<dim3(NNODES, NB), SDIM>>>(gb + (long)l * SDIM);
    }

    // belief projection
    k_out<<<(NB * NNODES * 32 + 255) / 256, 256>>>(wbp, bbp, out);
}

// round 2
// speedup vs baseline: 1.1319x; 1.1319x over previous
#include <cuda_runtime.h>

// Problem constants (fixed by the dataset)
#define NB       2        // batch
#define SDIM     256      // S
#define FDIM     512      // F1 = F2
#define NNODES   20000    // N
#define NE_      320000   // E
#define NLAYERS  3
#define BSJ      512      // NB * SDIM

// ---------------- scratch (device globals; no runtime allocation) ----------
__device__ float g_nsum[(size_t)NNODES * FDIM];        // 41 MB
__device__ float g_CT  [(size_t)BSJ * FDIM];           // 1 MB  CT[j][f2]
__device__ float g_dvec[BSJ];
__device__ float g_hA  [(size_t)NB * NNODES * SDIM];   // 41 MB (h)
__device__ float g_hB  [(size_t)NB * NNODES * SDIM];   // 41 MB (hw)
__device__ float g_WT  [(size_t)NLAYERS * SDIM * SDIM];// transposed layer weights [l][out][in]
__device__ int   g_deg [NNODES];
__device__ int   g_off [NNODES + 1];
__device__ int   g_cur [NNODES];
__device__ int   g_srcs[NE_];
__device__ float g_dinv[NNODES];

// ---------------- CSR build ------------------------------------------------
__global__ void k_init_deg() {
    int i = blockIdx.x * blockDim.x + threadIdx.x;
    if (i < NNODES) g_deg[i] = 1;   // self loop
}

__global__ void k_hist(const int* __restrict__ ei) {
    int e = blockIdx.x * blockDim.x + threadIdx.x;
    if (e < NE_) atomicAdd(&g_deg[ei[NE_ + e]], 1);
}

__global__ void k_scan() {
    __shared__ int ssum[512];
    int tid = threadIdx.x;
    const int CH = (NNODES + 511) / 512;
    int base = tid * CH;
    int s = 0;
    for (int i = 0; i < CH; ++i) {
        int idx = base + i;
        if (idx < NNODES) s += g_deg[idx] - 1;
    }
    ssum[tid] = s;
    __syncthreads();
    for (int off = 1; off < 512; off <<= 1) {
        int v = ssum[tid];
        int u = (tid >= off) ? ssum[tid - off] : 0;
        __syncthreads();
        ssum[tid] = v + u;
        __syncthreads();
    }
    int run = (tid == 0) ? 0 : ssum[tid - 1];
    for (int i = 0; i < CH; ++i) {
        int idx = base + i;
        if (idx < NNODES) {
            g_off[idx] = run;
            g_cur[idx] = run;
            g_dinv[idx] = rsqrtf((float)g_deg[idx]);
            run += g_deg[idx] - 1;
        }
    }
    if (tid == 511) g_off[NNODES] = run;
}

__global__ void k_scatter(const int* __restrict__ ei) {
    int e = blockIdx.x * blockDim.x + threadIdx.x;
    if (e < NE_) {
        int d = ei[NE_ + e];
        int p = atomicAdd(&g_cur[d], 1);
        g_srcs[p] = ei[e];
    }
}

// ---------------- nsum[n,f] = nodes[n,0,f] + nodes[n,1,f] ------------------
__global__ void k_nsum(const float* __restrict__ nodes) {
    long i = (long)blockIdx.x * blockDim.x + threadIdx.x;
    const long total = (long)NNODES * FDIM / 4;
    if (i >= total) return;
    const float4* nd = (const float4*)nodes;
    float4* ns = (float4*)g_nsum;
    long n = i / (FDIM / 4);
    long f = i % (FDIM / 4);
    float4 a = nd[n * (2 * FDIM / 4) + f];
    float4 b = nd[n * (2 * FDIM / 4) + FDIM / 4 + f];
    ns[i] = make_float4(a.x + b.x, a.y + b.y, a.z + b.z, a.w + b.w);
}

// ---------------- dvec[j] = 2 * sum_k bp[k]*x[j,k] -------------------------
__global__ void k_dvec(const float* __restrict__ x, const float* __restrict__ bp) {
    __shared__ float sh[256];
    int j = blockIdx.x;
    float s = 0.f;
    for (int k = threadIdx.x; k < FDIM; k += 256)
        s += bp[k] * x[(long)j * FDIM + k];
    sh[threadIdx.x] = s;
    __syncthreads();
    for (int o = 128; o > 0; o >>= 1) {
        if (threadIdx.x < o) sh[threadIdx.x] += sh[threadIdx.x + o];
        __syncthreads();
    }
    if (threadIdx.x == 0) g_dvec[j] = 2.f * sh[0];
}

// ---------------- weight transpose: WT[l][o][i] = gW[l][i][o] --------------
__global__ void k_wt(const float* __restrict__ gW) {
    int idx = blockIdx.x * blockDim.x + threadIdx.x;
    if (idx >= NLAYERS * SDIM * SDIM) return;
    int l = idx / (SDIM * SDIM);
    int r = idx % (SDIM * SDIM);
    int i = r >> 8, o = r & 255;
    g_WT[(long)l * SDIM * SDIM + o * SDIM + i] = gW[idx];
}

// ---------------- small SIMT SGEMM (kept for CT only) ----------------------
__global__ __launch_bounds__(256) void sgemm_nn(
    const float* __restrict__ A, const float* __restrict__ B, float* __restrict__ C,
    int M, int N, int K)
{
    __shared__ float As[8][128];
    __shared__ float Bs[8][128];
    int tid = threadIdx.x;
    int brow = blockIdx.x * 128;
    int bcol = blockIdx.y * 128;
    int tr = (tid / 16) * 8;
    int tc = (tid % 16) * 8;
    float acc[8][8] = {};
    int arow = tid / 2, acol = (tid % 2) * 4;
    int brl = tid / 32, bcl = (tid % 32) * 4;

    for (int k0 = 0; k0 < K; k0 += 8) {
        int gr = brow + arow;
        float4 av = (gr < M) ? *(const float4*)(A + (long)gr * K + k0 + acol)
                             : make_float4(0, 0, 0, 0);
        As[acol + 0][arow] = av.x; As[acol + 1][arow] = av.y;
        As[acol + 2][arow] = av.z; As[acol + 3][arow] = av.w;
        float4 bv = *(const float4*)(B + (long)(k0 + brl) * N + bcol + bcl);
        *(float4*)&Bs[brl][bcl] = bv;
        __syncthreads();
#pragma unroll
        for (int k = 0; k < 8; ++k) {
            float ar[8], br[8];
#pragma unroll
            for (int i = 0; i < 8; ++i) ar[i] = As[k][tr + i];
#pragma unroll
            for (int i = 0; i < 8; ++i) br[i] = Bs[k][tc + i];
#pragma unroll
            for (int i = 0; i < 8; ++i)
#pragma unroll
                for (int j = 0; j < 8; ++j)
                    acc[i][j] = fmaf(ar[i], br[j], acc[i][j]);
        }
        __syncthreads();
    }
#pragma unroll
    for (int i = 0; i < 8; ++i) {
        int gr = brow + tr + i;
        if (gr < M) {
#pragma unroll
            for (int j = 0; j < 8; j += 4) {
                *(float4*)(C + (long)gr * N + bcol + tc + j) =
                    make_float4(acc[i][j], acc[i][j + 1], acc[i][j + 2], acc[i][j + 3]);
            }
        }
    }
}

// ---------------- TF32 tensor-core NT GEMM (3xTF32 split) ------------------
// C[M,N] = A[M,K] * B[N,K]^T ; 128x128x16 tile, 8 warps (2x4), 64x32 warp tile.
__device__ __forceinline__ unsigned tf32cvt(float x) {
    unsigned r;
    asm("cvt.rna.tf32.f32 %0, %1;" : "=r"(r) : "f"(x));
    return r;
}

__device__ __forceinline__ void mma8(float c[4], const unsigned a[4], const unsigned b[2]) {
    asm volatile(
        "mma.sync.aligned.m16n8k8.row.col.f32.tf32.tf32.f32 "
        "{%0,%1,%2,%3}, {%4,%5,%6,%7}, {%8,%9}, {%0,%1,%2,%3};"
        : "+f"(c[0]), "+f"(c[1]), "+f"(c[2]), "+f"(c[3])
        : "r"(a[0]), "r"(a[1]), "r"(a[2]), "r"(a[3]), "r"(b[0]), "r"(b[1]));
}

#define AST 136

__global__ __launch_bounds__(256) void mma_nt(
    const float* __restrict__ A, const float* __restrict__ B, float* __restrict__ Cout,
    int M, int N, int K, long sA, long sC, int h0, const float* __restrict__ dvec)
{
    A += (long)blockIdx.z * sA;
    __shared__ float Ah[16][AST], Al[16][AST], Bh[16][AST], Bl[16][AST];
    int t = threadIdx.x;
    int brow = blockIdx.x * 128, bcol = blockIdx.y * 128;
    int lane = t & 31, wid = t >> 5;
    int g = lane >> 2, tig = lane & 3;
    int wm = (wid & 1) * 64, wn = (wid >> 1) * 32;
    int arow = t >> 1, ak = (t & 1) * 8;

    float acc[4][4][4] = {};
    float4 ra[2], rb[2];

    const float* Aptr = A + (long)(brow + arow) * K + ak;
    const float* Bptr = B + (long)(bcol + arow) * K + ak;
    bool avalid = (brow + arow) < M;

    if (avalid) { ra[0] = *(const float4*)Aptr; ra[1] = *(const float4*)(Aptr + 4); }
    else        { ra[0] = make_float4(0,0,0,0); ra[1] = make_float4(0,0,0,0); }
    rb[0] = *(const float4*)Bptr; rb[1] = *(const float4*)(Bptr + 4);

    int nK = K >> 4;
    for (int it = 0; it < nK; ++it) {
        __syncthreads();
#pragma unroll
        for (int j = 0; j < 8; ++j) {
            float va = (j < 4) ? ((const float*)&ra[0])[j] : ((const float*)&ra[1])[j - 4];
            float ha = __uint_as_float(tf32cvt(va));
            Ah[ak + j][arow] = ha;
            Al[ak + j][arow] = va - ha;
            float vb = (j < 4) ? ((const float*)&rb[0])[j] : ((const float*)&rb[1])[j - 4];
            float hb = __uint_as_float(tf32cvt(vb));
            Bh[ak + j][arow] = hb;
            Bl[ak + j][arow] = vb - hb;
        }
        if (it + 1 < nK) {
            const float* Ap = Aptr + (it + 1) * 16;
            const float* Bp = Bptr + (it + 1) * 16;
            if (avalid) { ra[0] = *(const float4*)Ap; ra[1] = *(const float4*)(Ap + 4); }
            rb[0] = *(const float4*)Bp; rb[1] = *(const float4*)(Bp + 4);
        }
        __syncthreads();
#pragma unroll
        for (int ks = 0; ks < 16; ks += 8) {
            unsigned ah[4][4], al[4][4], bh[4][2], bl[4][2];
#pragma unroll
            for (int mi = 0; mi < 4; ++mi) {
                int m = wm + mi * 16 + g;
                ah[mi][0] = __float_as_uint(Ah[ks + tig][m]);
                ah[mi][1] = __float_as_uint(Ah[ks + tig][m + 8]);
                ah[mi][2] = __float_as_uint(Ah[ks + tig + 4][m]);
                ah[mi][3] = __float_as_uint(Ah[ks + tig + 4][m + 8]);
                al[mi][0] = __float_as_uint(Al[ks + tig][m]);
                al[mi][1] = __float_as_uint(Al[ks + tig][m + 8]);
                al[mi][2] = __float_as_uint(Al[ks + tig + 4][m]);
                al[mi][3] = __float_as_uint(Al[ks + tig + 4][m + 8]);
            }
#pragma unroll
            for (int ni = 0; ni < 4; ++ni) {
                int n = wn + ni * 8 + g;
                bh[ni][0] = __float_as_uint(Bh[ks + tig][n]);
                bh[ni][1] = __float_as_uint(Bh[ks + tig + 4][n]);
                bl[ni][0] = __float_as_uint(Bl[ks + tig][n]);
                bl[ni][1] = __float_as_uint(Bl[ks + tig + 4][n]);
            }
#pragma unroll
            for (int mi = 0; mi < 4; ++mi)
#pragma unroll
                for (int ni = 0; ni < 4; ++ni) {
                    mma8(acc[mi][ni], ah[mi], bh[ni]);
                    mma8(acc[mi][ni], ah[mi], bl[ni]);
                    mma8(acc[mi][ni], al[mi], bh[ni]);
                }
        }
    }

    // epilogue
    if (!h0) {
        float* C = Cout + (long)blockIdx.z * sC;
#pragma unroll
        for (int mi = 0; mi < 4; ++mi) {
            int r0 = brow + wm + mi * 16 + g;
#pragma unroll
            for (int ni = 0; ni < 4; ++ni) {
                int c0 = bcol + wn + ni * 8 + 2 * tig;
                if (r0 < M) {
                    C[(long)r0 * N + c0]     = acc[mi][ni][0];
                    C[(long)r0 * N + c0 + 1] = acc[mi][ni][1];
                }
                if (r0 + 8 < M) {
                    C[(long)(r0 + 8) * N + c0]     = acc[mi][ni][2];
                    C[(long)(r0 + 8) * N + c0 + 1] = acc[mi][ni][3];
                }
            }
        }
    } else {
        // h[b][n][s] layout: col j = bcol.. -> b = j>>8, s = j&255 ; add dvec[j]
        int b = bcol >> 8;
        float* C = Cout + (long)b * NNODES * SDIM;
#pragma unroll
        for (int mi = 0; mi < 4; ++mi) {
            int r0 = brow + wm + mi * 16 + g;
#pragma unroll
            for (int ni = 0; ni < 4; ++ni) {
                int c0 = bcol + wn + ni * 8 + 2 * tig;
                int s0 = c0 & 255;
                float d0 = dvec[c0], d1 = dvec[c0 + 1];
                if (r0 < M) {
                    float* p = C + (long)r0 * SDIM + s0;
                    p[0] = acc[mi][ni][0] + d0;
                    p[1] = acc[mi][ni][1] + d1;
                }
                if (r0 + 8 < M) {
                    float* p = C + (long)(r0 + 8) * SDIM + s0;
                    p[0] = acc[mi][ni][2] + d0;
                    p[1] = acc[mi][ni][3] + d1;
                }
            }
        }
    }
}

// ---------------- CSR aggregation + bias + leaky relu ----------------------
__global__ void k_agg(const float* __restrict__ bias) {
    int t = blockIdx.x;
    int b = blockIdx.y;
    int s = threadIdx.x;
    float dt = g_dinv[t];
    long base = (long)b * NNODES * SDIM;
    float acc = g_hB[base + (long)t * SDIM + s] * dt * dt;   // self loop
    int e0 = g_off[t], e1 = g_off[t + 1];
    for (int e = e0; e < e1; ++e) {
        int src = g_srcs[e];
        float w = g_dinv[src] * dt;
        acc = fmaf(g_hB[base + (long)src * SDIM + s], w, acc);
    }
    acc += bias[s];
    g_hA[base + (long)t * SDIM + s] = acc > 0.f ? acc : 0.01f * acc;
}

// ---------------- output: out[b,n] = sum_s h[b,n,s]*wbp[s] + bbp -----------
__global__ void k_out(const float* __restrict__ wbp, const float* __restrict__ bbp,
                      float* __restrict__ out) {
    int gw = (blockIdx.x * blockDim.x + threadIdx.x) >> 5;
    int lane = threadIdx.x & 31;
    if (gw >= NB * NNODES) return;
    int b = gw / NNODES, n = gw % NNODES;
    const float* hr = g_hA + ((long)b * NNODES + n) * SDIM;
    float s = 0.f;
#pragma unroll
    for (int k = lane; k < SDIM; k += 32) s = fmaf(hr[k], wbp[k], s);
#pragma unroll
    for (int o = 16; o; o >>= 1) s += __shfl_xor_sync(0xffffffffu, s, o);
    if (lane == 0) out[(long)b * NNODES + n] = s + bbp[0];
}

// ---------------- launcher -------------------------------------------------
extern "C" void kernel_launch(void* const* d_in, const int* in_sizes, int n_in,
                              void* d_out, int out_size) {
    const float* x     = (const float*)d_in[0];   // [B,S,F]
    const float* nodes = (const float*)d_in[1];   // [N,2,F]
    const int*   ei    = (const int*)  d_in[2];   // [2,E]
    const float* Wp    = (const float*)d_in[3];   // [F,F]
    const float* bp    = (const float*)d_in[4];   // [F]
    const float* gW    = (const float*)d_in[5];   // [L,S,S]
    const float* gb    = (const float*)d_in[6];   // [L,S]
    const float* wbp   = (const float*)d_in[7];   // [S]
    const float* bbp   = (const float*)d_in[8];   // [1]
    float* out = (float*)d_out;

    void *pCT, *pHA, *pHB, *pNS, *pWT, *pDV;
    cudaGetSymbolAddress(&pCT, g_CT);
    cudaGetSymbolAddress(&pHA, g_hA);
    cudaGetSymbolAddress(&pHB, g_hB);
    cudaGetSymbolAddress(&pNS, g_nsum);
    cudaGetSymbolAddress(&pWT, g_WT);
    cudaGetSymbolAddress(&pDV, g_dvec);
    float* CTp = (float*)pCT;
    float* hAp = (float*)pHA;
    float* hBp = (float*)pHB;
    float* NSp = (float*)pNS;
    float* WTp = (float*)pWT;
    float* DVp = (float*)pDV;

    // CSR build
    k_init_deg<<<(NNODES + 255) / 256, 256>>>();
    k_hist<<<(NE_ + 255) / 256, 256>>>(ei);
    k_scan<<<1, 512>>>();
    k_scatter<<<(NE_ + 255) / 256, 256>>>(ei);

    // front-end
    k_nsum<<<(int)(((long)NNODES * FDIM / 4 + 255) / 256), 256>>>(nodes);
    sgemm_nn<<<dim3(4, 4, 1), 256>>>(x, Wp, CTp, BSJ, FDIM, FDIM);   // CT (small)
    k_dvec<<<BSJ, 256>>>(x, bp);
    k_wt<<<(NLAYERS * SDIM * SDIM + 255) / 256, 256>>>(gW);

    const int MB = (NNODES + 127) / 128;   // 157

    // H0: h = nsum @ CT^T + dvec  -> g_hA
    mma_nt<<<dim3(MB, BSJ / 128, 1), 256>>>(NSp, CTp, hAp,
                                            NNODES, BSJ, FDIM, 0, 0, 1, DVp);

    // GCN layers
    const long slab = (long)NNODES * SDIM;
    for (int l = 0; l < NLAYERS; ++l) {
        mma_nt<<<dim3(MB, SDIM / 128, NB), 256>>>(
            hAp, WTp + (long)l * SDIM * SDIM, hBp,
            NNODES, SDIM, SDIM, slab, slab, 0, nullptr);
        k_agg<<<dim3(NNODES, NB), SDIM>>>(gb + (long)l * SDIM);
    }

    // belief projection
    k_out<<<(NB * NNODES * 32 + 255) / 256, 256>>>(wbp, bbp, out);
}

// round 3
// speedup vs baseline: 1.6280x; 1.4384x over previous
#include <cuda_runtime.h>

// Problem constants (fixed by the dataset)
#define NB       2        // batch
#define SDIM     256      // S
#define FDIM     512      // F1 = F2
#define NNODES   20000    // N
#define NE_      320000   // E
#define NLAYERS  3
#define BSJ      512      // NB * SDIM

// ---------------- scratch (device globals; no runtime allocation) ----------
__device__ float g_nsum[(size_t)NNODES * FDIM];        // 41 MB
__device__ float g_CT  [(size_t)BSJ * FDIM];           // 1 MB  CT[j][f2]
__device__ float g_WpT [(size_t)FDIM * FDIM];          // 1 MB  Wp^T [f2][k]
__device__ float g_dvec[BSJ];
__device__ float g_hA  [(size_t)NB * NNODES * SDIM];   // 41 MB (h)
__device__ float g_hB  [(size_t)NB * NNODES * SDIM];   // 41 MB (hw)
__device__ float g_WT  [(size_t)NLAYERS * SDIM * SDIM];// transposed layer weights [l][out][in]
__device__ int   g_deg [NNODES];
__device__ int   g_off [NNODES + 1];
__device__ int   g_cur [NNODES];
__device__ int   g_srcs[NE_];
__device__ float g_dinv[NNODES];

// ---------------- CSR build ------------------------------------------------
__global__ void k_init_deg() {
    int i = blockIdx.x * blockDim.x + threadIdx.x;
    if (i < NNODES) g_deg[i] = 1;   // self loop
}

__global__ void k_hist(const int* __restrict__ ei) {
    int e = blockIdx.x * blockDim.x + threadIdx.x;
    if (e < NE_) atomicAdd(&g_deg[ei[NE_ + e]], 1);
}

__global__ void k_scan() {
    __shared__ int ssum[512];
    int tid = threadIdx.x;
    const int CH = (NNODES + 511) / 512;
    int base = tid * CH;
    int s = 0;
    for (int i = 0; i < CH; ++i) {
        int idx = base + i;
        if (idx < NNODES) s += g_deg[idx] - 1;
    }
    ssum[tid] = s;
    __syncthreads();
    for (int off = 1; off < 512; off <<= 1) {
        int v = ssum[tid];
        int u = (tid >= off) ? ssum[tid - off] : 0;
        __syncthreads();
        ssum[tid] = v + u;
        __syncthreads();
    }
    int run = (tid == 0) ? 0 : ssum[tid - 1];
    for (int i = 0; i < CH; ++i) {
        int idx = base + i;
        if (idx < NNODES) {
            g_off[idx] = run;
            g_cur[idx] = run;
            g_dinv[idx] = rsqrtf((float)g_deg[idx]);
            run += g_deg[idx] - 1;
        }
    }
    if (tid == 511) g_off[NNODES] = run;
}

__global__ void k_scatter(const int* __restrict__ ei) {
    int e = blockIdx.x * blockDim.x + threadIdx.x;
    if (e < NE_) {
        int d = ei[NE_ + e];
        int p = atomicAdd(&g_cur[d], 1);
        g_srcs[p] = ei[e];
    }
}

// ---------------- nsum[n,f] = nodes[n,0,f] + nodes[n,1,f] ------------------
__global__ void k_nsum(const float* __restrict__ nodes) {
    long i = (long)blockIdx.x * blockDim.x + threadIdx.x;
    const long total = (long)NNODES * FDIM / 4;
    if (i >= total) return;
    const float4* nd = (const float4*)nodes;
    float4* ns = (float4*)g_nsum;
    long n = i / (FDIM / 4);
    long f = i % (FDIM / 4);
    float4 a = nd[n * (2 * FDIM / 4) + f];
    float4 b = nd[n * (2 * FDIM / 4) + FDIM / 4 + f];
    ns[i] = make_float4(a.x + b.x, a.y + b.y, a.z + b.z, a.w + b.w);
}

// ---------------- dvec[j] = 2 * sum_k bp[k]*x[j,k] -------------------------
__global__ void k_dvec(const float* __restrict__ x, const float* __restrict__ bp) {
    __shared__ float sh[256];
    int j = blockIdx.x;
    float s = 0.f;
    for (int k = threadIdx.x; k < FDIM; k += 256)
        s += bp[k] * x[(long)j * FDIM + k];
    sh[threadIdx.x] = s;
    __syncthreads();
    for (int o = 128; o > 0; o >>= 1) {
        if (threadIdx.x < o) sh[threadIdx.x] += sh[threadIdx.x + o];
        __syncthreads();
    }
    if (threadIdx.x == 0) g_dvec[j] = 2.f * sh[0];
}

// ---------------- weight transpose: WT[l][o][i] = gW[l][i][o] --------------
__global__ void k_wt(const float* __restrict__ gW) {
    int idx = blockIdx.x * blockDim.x + threadIdx.x;
    if (idx >= NLAYERS * SDIM * SDIM) return;
    int l = idx / (SDIM * SDIM);
    int r = idx % (SDIM * SDIM);
    int i = r >> 8, o = r & 255;
    g_WT[(long)l * SDIM * SDIM + o * SDIM + i] = gW[idx];
}

// WpT[f2][k] = Wp[k][f2]
__global__ void k_wpT(const float* __restrict__ Wp) {
    int idx = blockIdx.x * blockDim.x + threadIdx.x;
    if (idx >= FDIM * FDIM) return;
    int k = idx / FDIM, f2 = idx % FDIM;
    g_WpT[(long)f2 * FDIM + k] = Wp[idx];
}

// ---------------- TF32 tensor-core NT GEMM (3xTF32 split) ------------------
// C[M,N] = A[M,K] * B[N,K]^T ; 128x128 tile, KSTEP=8, 8 warps (2x4 grid),
// 64x32 warp tile, cp.async double-buffered, hi/lo split in registers.
__device__ __forceinline__ float tf32f(float x) {
    unsigned r;
    asm("cvt.rna.tf32.f32 %0, %1;" : "=r"(r) : "f"(x));
    return __uint_as_float(r);
}

__device__ __forceinline__ void mma8(float c[4], const unsigned a[4], const unsigned b[2]) {
    asm volatile(
        "mma.sync.aligned.m16n8k8.row.col.f32.tf32.tf32.f32 "
        "{%0,%1,%2,%3}, {%4,%5,%6,%7}, {%8,%9}, {%0,%1,%2,%3};"
        : "+f"(c[0]), "+f"(c[1]), "+f"(c[2]), "+f"(c[3])
        : "r"(a[0]), "r"(a[1]), "r"(a[2]), "r"(a[3]), "r"(b[0]), "r"(b[1]));
}

__device__ __forceinline__ void cpasync16(float* dst, const float* src, int nbytes) {
    unsigned d = (unsigned)__cvta_generic_to_shared(dst);
    asm volatile("cp.async.cg.shared.global [%0], [%1], 16, %2;\n"
                 :: "r"(d), "l"(src), "r"(nbytes));
}

#define ASTR 12   // smem row stride in floats: 48B (16B-multiple, conflict-free)

__global__ __launch_bounds__(256) void mma_nt(
    const float* __restrict__ A, const float* __restrict__ B, float* __restrict__ Cout,
    int M, int N, int K, long sA, long sC, int h0, const float* __restrict__ dvec)
{
    A += (long)blockIdx.z * sA;
    __shared__ float As[2][128 * ASTR];
    __shared__ float Bs[2][128 * ASTR];
    int t = threadIdx.x;
    int brow = blockIdx.x * 128, bcol = blockIdx.y * 128;
    int lane = t & 31, wid = t >> 5;
    int g = lane >> 2, tig = lane & 3;
    int wm = (wid & 1) * 64, wn = (wid >> 1) * 32;

    // cp.async assignment: thread -> (row, 4-float chunk)
    int crow = t >> 1;
    int ckq  = (t & 1) * 4;
    const float* Asrc = A + (long)(brow + crow) * K + ckq;
    const float* Bsrc = B + (long)(bcol + crow) * K + ckq;
    int aval = ((brow + crow) < M) ? 16 : 0;   // zero-fill OOB rows
    int adst = crow * ASTR + ckq;

    float acc[4][4][4] = {};
    int nK = K >> 3;

    // prologue: stage 0
    cpasync16(&As[0][adst], Asrc, aval);
    cpasync16(&Bs[0][adst], Bsrc, 16);
    asm volatile("cp.async.commit_group;\n");

    for (int it = 0; it < nK; ++it) {
        asm volatile("cp.async.wait_group 0;\n");
        __syncthreads();
        if (it + 1 < nK) {
            int s = (it + 1) & 1;
            const float* Ap = Asrc + (it + 1) * 8;
            const float* Bp = Bsrc + (it + 1) * 8;
            cpasync16(&As[s][adst], Ap, aval);
            cpasync16(&Bs[s][adst], Bp, 16);
            asm volatile("cp.async.commit_group;\n");
        }
        const float* as = As[it & 1];
        const float* bs = Bs[it & 1];

        unsigned ah[4][4], al[4][4], bh[4][2], bl[4][2];
#pragma unroll
        for (int mi = 0; mi < 4; ++mi) {
            int m = wm + mi * 16 + g;
            float r0 = as[m * ASTR + tig];
            float r1 = as[(m + 8) * ASTR + tig];
            float r2 = as[m * ASTR + tig + 4];
            float r3 = as[(m + 8) * ASTR + tig + 4];
            float h0v = tf32f(r0), h1v = tf32f(r1), h2v = tf32f(r2), h3v = tf32f(r3);
            ah[mi][0] = __float_as_uint(h0v); al[mi][0] = __float_as_uint(r0 - h0v);
            ah[mi][1] = __float_as_uint(h1v); al[mi][1] = __float_as_uint(r1 - h1v);
            ah[mi][2] = __float_as_uint(h2v); al[mi][2] = __float_as_uint(r2 - h2v);
            ah[mi][3] = __float_as_uint(h3v); al[mi][3] = __float_as_uint(r3 - h3v);
        }
#pragma unroll
        for (int ni = 0; ni < 4; ++ni) {
            int n = wn + ni * 8 + g;
            float r0 = bs[n * ASTR + tig];
            float r1 = bs[n * ASTR + tig + 4];
            float h0v = tf32f(r0), h1v = tf32f(r1);
            bh[ni][0] = __float_as_uint(h0v); bl[ni][0] = __float_as_uint(r0 - h0v);
            bh[ni][1] = __float_as_uint(h1v); bl[ni][1] = __float_as_uint(r1 - h1v);
        }
#pragma unroll
        for (int mi = 0; mi < 4; ++mi)
#pragma unroll
            for (int ni = 0; ni < 4; ++ni) {
                mma8(acc[mi][ni], ah[mi], bh[ni]);
                mma8(acc[mi][ni], ah[mi], bl[ni]);
                mma8(acc[mi][ni], al[mi], bh[ni]);
            }
    }

    // epilogue
    if (!h0) {
        float* C = Cout + (long)blockIdx.z * sC;
#pragma unroll
        for (int mi = 0; mi < 4; ++mi) {
            int r0 = brow + wm + mi * 16 + g;
#pragma unroll
            for (int ni = 0; ni < 4; ++ni) {
                int c0 = bcol + wn + ni * 8 + 2 * tig;
                if (r0 < M) {
                    C[(long)r0 * N + c0]     = acc[mi][ni][0];
                    C[(long)r0 * N + c0 + 1] = acc[mi][ni][1];
                }
                if (r0 + 8 < M) {
                    C[(long)(r0 + 8) * N + c0]     = acc[mi][ni][2];
                    C[(long)(r0 + 8) * N + c0 + 1] = acc[mi][ni][3];
                }
            }
        }
    } else {
        // h[b][n][s]: col j -> b = j>>8, s = j&255 ; add dvec[j]
        int b = bcol >> 8;
        float* C = Cout + (long)b * NNODES * SDIM;
#pragma unroll
        for (int mi = 0; mi < 4; ++mi) {
            int r0 = brow + wm + mi * 16 + g;
#pragma unroll
            for (int ni = 0; ni < 4; ++ni) {
                int c0 = bcol + wn + ni * 8 + 2 * tig;
                int s0 = c0 & 255;
                float d0 = dvec[c0], d1 = dvec[c0 + 1];
                if (r0 < M) {
                    float* p = C + (long)r0 * SDIM + s0;
                    p[0] = acc[mi][ni][0] + d0;
                    p[1] = acc[mi][ni][1] + d1;
                }
                if (r0 + 8 < M) {
                    float* p = C + (long)(r0 + 8) * SDIM + s0;
                    p[0] = acc[mi][ni][2] + d0;
                    p[1] = acc[mi][ni][3] + d1;
                }
            }
        }
    }
}

// ---------------- CSR aggregation + bias + leaky relu (float4) -------------
// block = 64 threads, one (node, batch); each thread owns 4 consecutive s.
__global__ void k_agg(const float* __restrict__ bias) {
    int node = blockIdx.x;
    int b = blockIdx.y;
    int tid = threadIdx.x;                 // 0..63
    float dt = g_dinv[node];
    long base4 = (long)b * NNODES * (SDIM / 4);
    const float4* hB4 = (const float4*)g_hB + base4;
    float4* hA4 = (float4*)g_hA + base4;

    float4 v = hB4[(long)node * 64 + tid];
    float sw = dt * dt;
    float4 acc = make_float4(v.x * sw, v.y * sw, v.z * sw, v.w * sw);
    int e0 = g_off[node], e1 = g_off[node + 1];
    for (int e = e0; e < e1; ++e) {
        int src = g_srcs[e];
        float w = g_dinv[src] * dt;
        float4 u = hB4[(long)src * 64 + tid];
        acc.x = fmaf(u.x, w, acc.x);
        acc.y = fmaf(u.y, w, acc.y);
        acc.z = fmaf(u.z, w, acc.z);
        acc.w = fmaf(u.w, w, acc.w);
    }
    float4 bb = ((const float4*)bias)[tid];
    acc.x += bb.x; acc.y += bb.y; acc.z += bb.z; acc.w += bb.w;
    acc.x = acc.x > 0.f ? acc.x : 0.01f * acc.x;
    acc.y = acc.y > 0.f ? acc.y : 0.01f * acc.y;
    acc.z = acc.z > 0.f ? acc.z : 0.01f * acc.z;
    acc.w = acc.w > 0.f ? acc.w : 0.01f * acc.w;
    hA4[(long)node * 64 + tid] = acc;
}

// ---------------- output: out[b,n] = sum_s h[b,n,s]*wbp[s] + bbp -----------
__global__ void k_out(const float* __restrict__ wbp, const float* __restrict__ bbp,
                      float* __restrict__ out) {
    int gw = (blockIdx.x * blockDim.x + threadIdx.x) >> 5;
    int lane = threadIdx.x & 31;
    if (gw >= NB * NNODES) return;
    int b = gw / NNODES, n = gw % NNODES;
    const float* hr = g_hA + ((long)b * NNODES + n) * SDIM;
    float s = 0.f;
#pragma unroll
    for (int k = lane; k < SDIM; k += 32) s = fmaf(hr[k], wbp[k], s);
#pragma unroll
    for (int o = 16; o; o >>= 1) s += __shfl_xor_sync(0xffffffffu, s, o);
    if (lane == 0) out[(long)b * NNODES + n] = s + bbp[0];
}

// ---------------- launcher -------------------------------------------------
extern "C" void kernel_launch(void* const* d_in, const int* in_sizes, int n_in,
                              void* d_out, int out_size) {
    const float* x     = (const float*)d_in[0];   // [B,S,F]
    const float* nodes = (const float*)d_in[1];   // [N,2,F]
    const int*   ei    = (const int*)  d_in[2];   // [2,E]
    const float* Wp    = (const float*)d_in[3];   // [F,F]
    const float* bp    = (const float*)d_in[4];   // [F]
    const float* gW    = (const float*)d_in[5];   // [L,S,S]
    const float* gb    = (const float*)d_in[6];   // [L,S]
    const float* wbp   = (const float*)d_in[7];   // [S]
    const float* bbp   = (const float*)d_in[8];   // [1]
    float* out = (float*)d_out;

    void *pCT, *pHA, *pHB, *pNS, *pWT, *pDV, *pWpT;
    cudaGetSymbolAddress(&pCT, g_CT);
    cudaGetSymbolAddress(&pHA, g_hA);
    cudaGetSymbolAddress(&pHB, g_hB);
    cudaGetSymbolAddress(&pNS, g_nsum);
    cudaGetSymbolAddress(&pWT, g_WT);
    cudaGetSymbolAddress(&pDV, g_dvec);
    cudaGetSymbolAddress(&pWpT, g_WpT);
    float* CTp = (float*)pCT;
    float* hAp = (float*)pHA;
    float* hBp = (float*)pHB;
    float* NSp = (float*)pNS;
    float* WTp = (float*)pWT;
    float* DVp = (float*)pDV;
    float* WpTp = (float*)pWpT;

    // CSR build
    k_init_deg<<<(NNODES + 255) / 256, 256>>>();
    k_hist<<<(NE_ + 255) / 256, 256>>>(ei);
    k_scan<<<1, 512>>>();
    k_scatter<<<(NE_ + 255) / 256, 256>>>(ei);

    // front-end
    k_nsum<<<(int)(((long)NNODES * FDIM / 4 + 255) / 256), 256>>>(nodes);
    k_wpT<<<(FDIM * FDIM + 255) / 256, 256>>>(Wp);
    k_dvec<<<BSJ, 256>>>(x, bp);
    k_wt<<<(NLAYERS * SDIM * SDIM + 255) / 256, 256>>>(gW);

    // CT[j,f2] = sum_k x[j,k]*Wp[k,f2]  (NT with B = Wp^T)
    mma_nt<<<dim3(BSJ / 128, FDIM / 128, 1), 256>>>(x, WpTp, CTp,
                                                    BSJ, FDIM, FDIM, 0, 0, 0, nullptr);

    const int MB = (NNODES + 127) / 128;   // 157

    // H0: h = nsum @ CT^T + dvec -> g_hA
    mma_nt<<<dim3(MB, BSJ / 128, 1), 256>>>(NSp, CTp, hAp,
                                            NNODES, BSJ, FDIM, 0, 0, 1, DVp);

    // GCN layers
    const long slab = (long)NNODES * SDIM;
    for (int l = 0; l < NLAYERS; ++l) {
        mma_nt<<<dim3(MB, SDIM / 128, NB), 256>>>(
            hAp, WTp + (long)l * SDIM * SDIM, hBp,
            NNODES, SDIM, SDIM, slab, slab, 0, nullptr);
        k_agg<<<dim3(NNODES, NB), 64>>>(gb + (long)l * SDIM);
    }

    // belief projection
    k_out<<<(NB * NNODES * 32 + 255) / 256, 256>>>(wbp, bbp, out);
}